// round 2
// baseline (speedup 1.0000x reference)
#include <cuda_runtime.h>
#include <math.h>
#include <stdint.h>

// Problem dims (static per dataset)
#define NA 500000
#define NC 250000
#define NE 1000000
#define NB 2048
#define DD 256
#define NH 4
// per-head: C=64, 2C=128

// ---------------- scratch (static __device__, no allocs) ----------------
__device__ __align__(16) float g_hx[(size_t)NC * DD];
__device__ int      g_idx[2 * NE];           // normalized int32 indices [row | col]
__device__ int      g_cb[NC];                // normalized int32 clique_batch
__device__ int      g_cnt[NC];
__device__ int      g_off[NC + 1];
__device__ int      g_fill[NC];
__device__ int      g_csr[NE];
__device__ int      g_part[256];
__device__ float    g_score[NC * NH];
__device__ unsigned g_mxu[NB * NH];
__device__ float    g_den[NB * NH];
__device__ int      g_is32;

// ---------------- helpers ----------------
__device__ __forceinline__ unsigned f2u_ord(float f) {
    unsigned u = __float_as_uint(f);
    return (u & 0x80000000u) ? ~u : (u | 0x80000000u);
}
__device__ __forceinline__ float u2f_ord(unsigned u) {
    return (u & 0x80000000u) ? __uint_as_float(u ^ 0x80000000u)
                             : __uint_as_float(~u);
}
__device__ __forceinline__ int clampi(int v, int lo, int hi) {
    return v < lo ? lo : (v > hi ? hi : v);
}

// ---------------- -1: dtype detect + index normalization ----------------
__global__ void k_detect(const long long* __restrict__ a2c) {
    __shared__ int s;
    if (threadIdx.x == 0) s = 0;
    __syncthreads();
    long long v = a2c[threadIdx.x];  // 256 int64 reads = 2KB, safely in-bounds
    if (v < 0 || v >= 0x80000000LL) atomicOr(&s, 1);
    __syncthreads();
    if (threadIdx.x == 0) g_is32 = s;
}
__global__ void k_cvt(const void* __restrict__ a2c, const void* __restrict__ cb) {
    int i = blockIdx.x * blockDim.x + threadIdx.x;
    int is32 = g_is32;
    if (i < 2 * NE) {
        int v = is32 ? ((const int*)a2c)[i] : (int)(((const long long*)a2c)[i]);
        g_idx[i] = v;
    }
    if (i < NC) {
        int v = is32 ? ((const int*)cb)[i] : (int)(((const long long*)cb)[i]);
        g_cb[i] = clampi(v, 0, NB - 1);
    }
}

// ---------------- 0: init ----------------
__global__ void k_init(float* __restrict__ drug) {
    int i = blockIdx.x * blockDim.x + threadIdx.x;
    if (i < NB * DD) drug[i] = 0.f;
    if (i < NC) { g_cnt[i] = 0; g_fill[i] = 0; }
    if (i < NB * NH) { g_den[i] = 0.f; g_mxu[i] = f2u_ord(-3.0e38f); }
}

// ---------------- 1: histogram ----------------
__global__ void k_hist() {
    int i = blockIdx.x * blockDim.x + threadIdx.x;
    if (i >= NE) return;
    int c = clampi(g_idx[NE + i], 0, NC - 1);
    atomicAdd(&g_cnt[c], 1);
}

// ---------------- 2: exclusive scan (3-phase, 2048 elems/block) ----------------
__global__ void k_scan_a() {
    __shared__ int sums[256];
    int tid = threadIdx.x;
    int base = blockIdx.x * 2048 + tid * 8;
    int v[8], pre[8];
    int s = 0;
#pragma unroll
    for (int j = 0; j < 8; j++) {
        int idx = base + j;
        v[j] = (idx < NC) ? g_cnt[idx] : 0;
        pre[j] = s;
        s += v[j];
    }
    sums[tid] = s;
    __syncthreads();
    for (int off = 1; off < 256; off <<= 1) {
        int t = (tid >= off) ? sums[tid - off] : 0;
        __syncthreads();
        sums[tid] += t;
        __syncthreads();
    }
    int excl = (tid == 0) ? 0 : sums[tid - 1];
#pragma unroll
    for (int j = 0; j < 8; j++) {
        int idx = base + j;
        if (idx < NC) g_off[idx] = excl + pre[j];
    }
    if (tid == 255) g_part[blockIdx.x] = sums[255];
}
__global__ void k_scan_b(int nb) {
    if (threadIdx.x == 0) {
        int s = 0;
        for (int i = 0; i < nb; i++) { int t = g_part[i]; g_part[i] = s; s += t; }
    }
}
__global__ void k_scan_c() {
    int i = blockIdx.x * blockDim.x + threadIdx.x;
    if (i < NC) g_off[i] += g_part[i >> 11];
}

// ---------------- 3: CSR fill ----------------
__global__ void k_fill() {
    int i = blockIdx.x * blockDim.x + threadIdx.x;
    if (i >= NE) return;
    int c = clampi(g_idx[NE + i], 0, NC - 1);
    int r = clampi(g_idx[i], 0, NA - 1);
    int p = g_off[c] + atomicAdd(&g_fill[c], 1);
    if (p >= 0 && p < NE) g_csr[p] = r;
}

// ---------------- 4: gather + mean (one clique per 64-thread block) ----------------
__global__ void k_agg(const float* __restrict__ x) {
    int c = blockIdx.x;
    int t = threadIdx.x;  // 0..63, each owns one float4
    int deg = g_cnt[c];
    int st  = g_off[c];
    float4 acc = make_float4(0.f, 0.f, 0.f, 0.f);
    int e = 0;
    for (; e + 2 <= deg; e += 2) {
        int r0 = g_csr[st + e], r1 = g_csr[st + e + 1];
        float4 a = ((const float4*)(x + (size_t)r0 * DD))[t];
        float4 b = ((const float4*)(x + (size_t)r1 * DD))[t];
        acc.x += a.x + b.x; acc.y += a.y + b.y;
        acc.z += a.z + b.z; acc.w += a.w + b.w;
    }
    if (e < deg) {
        int r0 = g_csr[st + e];
        float4 a = ((const float4*)(x + (size_t)r0 * DD))[t];
        acc.x += a.x; acc.y += a.y; acc.z += a.z; acc.w += a.w;
    }
    float inv = 1.f / (float)max(deg, 1);
    acc.x *= inv; acc.y *= inv; acc.z *= inv; acc.w *= inv;
    ((float4*)(g_hx + (size_t)c * DD))[t] = acc;
}

// ---------------- 5: xc = x_clique + relu(hx @ Wp + bp) ----------------
// 64x64 tile, BK=16, 256 threads, 4x4 micro-tile
__global__ void k_gemm_wp(const float* __restrict__ Wp,
                          const float* __restrict__ bp,
                          const float* __restrict__ xcl,
                          float* __restrict__ xc) {
    __shared__ float As[16][65];
    __shared__ float Bs[16][64];
    int tid = threadIdx.x;
    int tx = tid & 15, ty = tid >> 4;
    int bm = blockIdx.y * 64, bn = blockIdx.x * 64;
    int arow = tid >> 2, akq = tid & 3;
    int brow = tid >> 4, bnq = tid & 15;
    float acc[4][4] = {};
    for (int k0 = 0; k0 < DD; k0 += 16) {
        float4 av = make_float4(0.f, 0.f, 0.f, 0.f);
        int gm = bm + arow;
        if (gm < NC) av = *(const float4*)(g_hx + (size_t)gm * DD + k0 + akq * 4);
        float4 bv = *(const float4*)(Wp + (size_t)(k0 + brow) * DD + bn + bnq * 4);
        __syncthreads();
        As[akq * 4 + 0][arow] = av.x;
        As[akq * 4 + 1][arow] = av.y;
        As[akq * 4 + 2][arow] = av.z;
        As[akq * 4 + 3][arow] = av.w;
        *(float4*)&Bs[brow][bnq * 4] = bv;
        __syncthreads();
#pragma unroll
        for (int k = 0; k < 16; k++) {
            float a0 = As[k][ty * 4 + 0];
            float a1 = As[k][ty * 4 + 1];
            float a2 = As[k][ty * 4 + 2];
            float a3 = As[k][ty * 4 + 3];
            float4 b = *(const float4*)&Bs[k][tx * 4];
            acc[0][0] += a0 * b.x; acc[0][1] += a0 * b.y; acc[0][2] += a0 * b.z; acc[0][3] += a0 * b.w;
            acc[1][0] += a1 * b.x; acc[1][1] += a1 * b.y; acc[1][2] += a1 * b.z; acc[1][3] += a1 * b.w;
            acc[2][0] += a2 * b.x; acc[2][1] += a2 * b.y; acc[2][2] += a2 * b.z; acc[2][3] += a2 * b.w;
            acc[3][0] += a3 * b.x; acc[3][1] += a3 * b.y; acc[3][2] += a3 * b.z; acc[3][3] += a3 * b.w;
        }
    }
    int n0 = bn + tx * 4;
    float4 bpv = *(const float4*)(bp + n0);
#pragma unroll
    for (int i = 0; i < 4; i++) {
        int m = bm + ty * 4 + i;
        if (m >= NC) continue;
        float4 xv = *(const float4*)(xcl + (size_t)m * DD + n0);
        float4 r;
        r.x = xv.x + fmaxf(acc[i][0] + bpv.x, 0.f);
        r.y = xv.y + fmaxf(acc[i][1] + bpv.y, 0.f);
        r.z = xv.z + fmaxf(acc[i][2] + bpv.z, 0.f);
        r.w = xv.w + fmaxf(acc[i][3] + bpv.w, 0.f);
        *(float4*)(xc + (size_t)m * DD + n0) = r;
    }
}

// ---------------- 6: per-head MLP score ----------------
__global__ void k_mlp(const float* __restrict__ xc, const float* __restrict__ W1,
                      const float* __restrict__ b1, const float* __restrict__ W2,
                      const float* __restrict__ b2) {
    __shared__ float W1h[64][128];
    __shared__ float W2h[128], b1h[128];
    __shared__ float scs[4][4][64];
    int h = blockIdx.y;
    int tid = threadIdx.x, wid = tid >> 5, lane = tid & 31;
    const float* W1g = W1 + h * 8192;
    for (int i = tid; i < 8192; i += 128) ((float*)W1h)[i] = W1g[i];
    if (tid < 128) { W2h[tid] = W2[h * 128 + tid]; b1h[tid] = b1[h * 128 + tid]; }
    float b2h = b2[h];
    __syncthreads();
    int cbase0 = blockIdx.x * 128;
    for (int it = 0; it < 8; it++) {
        int cbase = cbase0 + it * 16 + wid * 4;
        __syncwarp();
#pragma unroll
        for (int t = 0; t < 4; t++) {
            int c = cbase + t;
            float v0 = 0.f, v1 = 0.f;
            if (c < NC) {
                v0 = xc[(size_t)c * DD + h * 64 + lane];
                v1 = xc[(size_t)c * DD + h * 64 + 32 + lane];
            }
            scs[wid][t][lane] = v0;
            scs[wid][t][32 + lane] = v1;
        }
        __syncwarp();
        float4 binit = *(const float4*)&b1h[lane * 4];
        float4 a0 = binit, a1 = binit, a2 = binit, a3 = binit;
#pragma unroll 8
        for (int cc = 0; cc < 64; cc++) {
            float4 w = *(const float4*)&W1h[cc][lane * 4];
            float s0 = scs[wid][0][cc];
            float s1 = scs[wid][1][cc];
            float s2 = scs[wid][2][cc];
            float s3 = scs[wid][3][cc];
            a0.x += s0 * w.x; a0.y += s0 * w.y; a0.z += s0 * w.z; a0.w += s0 * w.w;
            a1.x += s1 * w.x; a1.y += s1 * w.y; a1.z += s1 * w.z; a1.w += s1 * w.w;
            a2.x += s2 * w.x; a2.y += s2 * w.y; a2.z += s2 * w.z; a2.w += s2 * w.w;
            a3.x += s3 * w.x; a3.y += s3 * w.y; a3.z += s3 * w.z; a3.w += s3 * w.w;
        }
        float4 w2 = *(const float4*)&W2h[lane * 4];
        float r[4];
        r[0] = fmaxf(a0.x, 0.f) * w2.x + fmaxf(a0.y, 0.f) * w2.y + fmaxf(a0.z, 0.f) * w2.z + fmaxf(a0.w, 0.f) * w2.w;
        r[1] = fmaxf(a1.x, 0.f) * w2.x + fmaxf(a1.y, 0.f) * w2.y + fmaxf(a1.z, 0.f) * w2.z + fmaxf(a1.w, 0.f) * w2.w;
        r[2] = fmaxf(a2.x, 0.f) * w2.x + fmaxf(a2.y, 0.f) * w2.y + fmaxf(a2.z, 0.f) * w2.z + fmaxf(a2.w, 0.f) * w2.w;
        r[3] = fmaxf(a3.x, 0.f) * w2.x + fmaxf(a3.y, 0.f) * w2.y + fmaxf(a3.z, 0.f) * w2.z + fmaxf(a3.w, 0.f) * w2.w;
#pragma unroll
        for (int t = 0; t < 4; t++) {
#pragma unroll
            for (int o = 16; o; o >>= 1) r[t] += __shfl_xor_sync(0xFFFFFFFFu, r[t], o);
        }
        if (lane == 0) {
#pragma unroll
            for (int t = 0; t < 4; t++) {
                int c = cbase + t;
                if (c < NC) g_score[c * NH + h] = r[t] + b2h;
            }
        }
    }
}

// ---------------- 7: segment softmax ----------------
__global__ void k_segmax() {
    int i = blockIdx.x * blockDim.x + threadIdx.x;
    if (i >= NC * NH) return;
    int c = i >> 2, h = i & 3;
    int b = g_cb[c];
    atomicMax(&g_mxu[b * NH + h], f2u_ord(g_score[i]));
}
__global__ void k_segsum() {
    int i = blockIdx.x * blockDim.x + threadIdx.x;
    if (i >= NC * NH) return;
    int c = i >> 2, h = i & 3;
    int b = g_cb[c];
    float mx = u2f_ord(g_mxu[b * NH + h]);
    float e = expf(g_score[i] - mx);
    g_score[i] = e;
    atomicAdd(&g_den[b * NH + h], e);
}
__global__ void k_alpha(float* __restrict__ alpha_out) {
    int i = blockIdx.x * blockDim.x + threadIdx.x;
    if (i >= NC * NH) return;
    int c = i >> 2, h = i & 3;
    int b = g_cb[c];
    alpha_out[i] = g_score[i] / (g_den[b * NH + h] + 1e-16f);
}

// ---------------- 8: drug_feat segment-sum (sorted-run accumulation) ----------------
__global__ void k_final(const float* __restrict__ xc, const float* __restrict__ alpha,
                        float* __restrict__ drug) {
    int d = threadIdx.x;  // 256
    int hh = d >> 6;
    int c0 = blockIdx.x * 128;
    if (c0 >= NC) return;
    int cend = min(c0 + 128, NC);
    float acc = 0.f;
    int cur = g_cb[c0];
    for (int c = c0; c < cend; c++) {
        int b = g_cb[c];
        if (b != cur) {
            atomicAdd(&drug[(size_t)cur * DD + d], acc);
            acc = 0.f; cur = b;
        }
        acc += xc[(size_t)c * DD + d] * alpha[c * NH + hh];
    }
    atomicAdd(&drug[(size_t)cur * DD + d], acc);
}

// ---------------- launcher ----------------
extern "C" void kernel_launch(void* const* d_in, const int* in_sizes, int n_in,
                              void* d_out, int out_size) {
    const float* x    = (const float*)d_in[0];
    const float* xcl  = (const float*)d_in[1];
    const float* Wp   = (const float*)d_in[2];
    const float* bp   = (const float*)d_in[3];
    const float* W1   = (const float*)d_in[4];
    const float* b1   = (const float*)d_in[5];
    const float* W2   = (const float*)d_in[6];
    const float* b2   = (const float*)d_in[7];
    const void*  a2c  = d_in[8];
    const void*  cb   = d_in[9];
    // d_in[10] = clique_edge_index: unused by the reference

    float* out  = (float*)d_out;
    float* drug = out;                                      // [NB, DD]
    float* xc   = out + (size_t)NB * DD;                    // [NC, DD]
    float* alph = out + (size_t)NB * DD + (size_t)NC * DD;  // [NC, NH]

    k_detect<<<1, 256>>>((const long long*)a2c);
    k_cvt<<<(2 * NE + 255) / 256, 256>>>(a2c, cb);
    k_init<<<(NB * DD + 255) / 256, 256>>>(drug);
    k_hist<<<(NE + 255) / 256, 256>>>();
    int nscan = (NC + 2047) / 2048;
    k_scan_a<<<nscan, 256>>>();
    k_scan_b<<<1, 32>>>(nscan);
    k_scan_c<<<(NC + 255) / 256, 256>>>();
    k_fill<<<(NE + 255) / 256, 256>>>();
    k_agg<<<NC, 64>>>(x);
    {
        dim3 g(DD / 64, (NC + 63) / 64);
        k_gemm_wp<<<g, 256>>>(Wp, bp, xcl, xc);
    }
    {
        dim3 g((NC + 127) / 128, NH);
        k_mlp<<<g, 128>>>(xc, W1, b1, W2, b2);
    }
    k_segmax<<<(NC * NH + 255) / 256, 256>>>();
    k_segsum<<<(NC * NH + 255) / 256, 256>>>();
    k_alpha<<<(NC * NH + 255) / 256, 256>>>(alph);
    k_final<<<(NC + 127) / 128, 256>>>(xc, alph, drug);
}

// round 4
// speedup vs baseline: 1.6904x; 1.6904x over previous
#include <cuda_runtime.h>
#include <cuda_bf16.h>
#include <math.h>
#include <stdint.h>

// Problem dims (static per dataset)
#define NA 500000
#define NC 250000
#define NE 1000000
#define NB 2048
#define DD 256
#define NH 4

// ---------------- scratch (static __device__, no allocs) ----------------
__device__ __align__(16) __nv_bfloat16 g_hxh[(size_t)NC * DD];
__device__ __align__(16) __nv_bfloat16 g_hxl[(size_t)NC * DD];
__device__ __align__(16) __nv_bfloat16 g_wph[DD * DD];      // Wp^T hi  [N][K]
__device__ __align__(16) __nv_bfloat16 g_wpl[DD * DD];      // Wp^T lo  [N][K]
__device__ __align__(16) __nv_bfloat16 g_w1h[NH * 128 * 64]; // W1^T hi [h][n][k]
__device__ __align__(16) __nv_bfloat16 g_w1l[NH * 128 * 64]; // W1^T lo [h][n][k]
__device__ int      g_idx[2 * NE];
__device__ int      g_cb[NC];
__device__ int      g_cnt[NC];
__device__ int      g_off[NC + 1];
__device__ int      g_fill[NC];
__device__ int      g_csr[NE];
__device__ int      g_part[256];
__device__ float    g_score[NC * NH];
__device__ unsigned g_mxu[NB * NH];
__device__ float    g_den[NB * NH];
__device__ int      g_is32;

// ---------------- mma.sync wrapper (portable PTX, compute_80+) ----------------
__device__ __forceinline__ void mma_bf16(float* c, const uint32_t* a, const uint32_t* b) {
    asm volatile(
        "mma.sync.aligned.m16n8k16.row.col.f32.bf16.bf16.f32 "
        "{%0,%1,%2,%3}, {%4,%5,%6,%7}, {%8,%9}, {%0,%1,%2,%3};"
        : "+f"(c[0]), "+f"(c[1]), "+f"(c[2]), "+f"(c[3])
        : "r"(a[0]), "r"(a[1]), "r"(a[2]), "r"(a[3]), "r"(b[0]), "r"(b[1]));
}

// ---------------- misc helpers ----------------
__device__ __forceinline__ unsigned f2u_ord(float f) {
    unsigned u = __float_as_uint(f);
    return (u & 0x80000000u) ? ~u : (u | 0x80000000u);
}
__device__ __forceinline__ float u2f_ord(unsigned u) {
    return (u & 0x80000000u) ? __uint_as_float(u ^ 0x80000000u) : __uint_as_float(~u);
}
__device__ __forceinline__ int clampi(int v, int lo, int hi) {
    return v < lo ? lo : (v > hi ? hi : v);
}

// ---------------- -1: dtype detect + index normalization ----------------
__global__ void k_detect(const long long* __restrict__ a2c) {
    __shared__ int s;
    if (threadIdx.x == 0) s = 0;
    __syncthreads();
    long long v = a2c[threadIdx.x];
    if (v < 0 || v >= 0x80000000LL) atomicOr(&s, 1);
    __syncthreads();
    if (threadIdx.x == 0) g_is32 = s;
}
__global__ void k_cvt(const void* __restrict__ a2c, const void* __restrict__ cb) {
    int i = blockIdx.x * blockDim.x + threadIdx.x;
    int is32 = g_is32;
    if (i < 2 * NE) {
        int v = is32 ? ((const int*)a2c)[i] : (int)(((const long long*)a2c)[i]);
        g_idx[i] = v;
    }
    if (i < NC) {
        int v = is32 ? ((const int*)cb)[i] : (int)(((const long long*)cb)[i]);
        g_cb[i] = clampi(v, 0, NB - 1);
    }
}

// ---------------- 0: init ----------------
__global__ void k_init(float* __restrict__ drug) {
    int i = blockIdx.x * blockDim.x + threadIdx.x;
    if (i < NB * DD) drug[i] = 0.f;
    if (i < NC) { g_cnt[i] = 0; g_fill[i] = 0; }
    if (i < NB * NH) { g_den[i] = 0.f; g_mxu[i] = f2u_ord(-3.0e38f); }
}

// ---------------- 1: histogram ----------------
__global__ void k_hist() {
    int i = blockIdx.x * blockDim.x + threadIdx.x;
    if (i >= NE) return;
    atomicAdd(&g_cnt[clampi(g_idx[NE + i], 0, NC - 1)], 1);
}

// ---------------- 2: scan ----------------
__global__ void k_scan_a() {
    __shared__ int sums[256];
    int tid = threadIdx.x;
    int base = blockIdx.x * 2048 + tid * 8;
    int pre[8]; int s = 0;
#pragma unroll
    for (int j = 0; j < 8; j++) {
        int idx = base + j;
        int v = (idx < NC) ? g_cnt[idx] : 0;
        pre[j] = s; s += v;
    }
    sums[tid] = s;
    __syncthreads();
    for (int off = 1; off < 256; off <<= 1) {
        int t = (tid >= off) ? sums[tid - off] : 0;
        __syncthreads();
        sums[tid] += t;
        __syncthreads();
    }
    int excl = (tid == 0) ? 0 : sums[tid - 1];
#pragma unroll
    for (int j = 0; j < 8; j++) {
        int idx = base + j;
        if (idx < NC) g_off[idx] = excl + pre[j];
    }
    if (tid == 255) g_part[blockIdx.x] = sums[255];
}
__global__ void k_scan_b(int nb) {
    if (threadIdx.x == 0) {
        int s = 0;
        for (int i = 0; i < nb; i++) { int t = g_part[i]; g_part[i] = s; s += t; }
    }
}
__global__ void k_scan_c() {
    int i = blockIdx.x * blockDim.x + threadIdx.x;
    if (i < NC) g_off[i] += g_part[i >> 11];
}

// ---------------- 3: CSR fill ----------------
__global__ void k_fill() {
    int i = blockIdx.x * blockDim.x + threadIdx.x;
    if (i >= NE) return;
    int c = clampi(g_idx[NE + i], 0, NC - 1);
    int r = clampi(g_idx[i], 0, NA - 1);
    int p = g_off[c] + atomicAdd(&g_fill[c], 1);
    if (p >= 0 && p < NE) g_csr[p] = r;
}

// ---------------- 4: gather + mean -> split bf16 hi/lo ----------------
__global__ void k_agg(const float* __restrict__ x) {
    int c = blockIdx.x;
    int t = threadIdx.x;  // 0..63
    int deg = g_cnt[c];
    int st  = g_off[c];
    float4 acc = make_float4(0.f, 0.f, 0.f, 0.f);
    int e = 0;
    for (; e + 2 <= deg; e += 2) {
        int r0 = g_csr[st + e], r1 = g_csr[st + e + 1];
        float4 a = ((const float4*)(x + (size_t)r0 * DD))[t];
        float4 b = ((const float4*)(x + (size_t)r1 * DD))[t];
        acc.x += a.x + b.x; acc.y += a.y + b.y;
        acc.z += a.z + b.z; acc.w += a.w + b.w;
    }
    if (e < deg) {
        int r0 = g_csr[st + e];
        float4 a = ((const float4*)(x + (size_t)r0 * DD))[t];
        acc.x += a.x; acc.y += a.y; acc.z += a.z; acc.w += a.w;
    }
    float inv = 1.f / (float)max(deg, 1);
    float f[4] = { acc.x * inv, acc.y * inv, acc.z * inv, acc.w * inv };
    __nv_bfloat16 h[4], l[4];
#pragma unroll
    for (int i = 0; i < 4; i++) {
        h[i] = __float2bfloat16(f[i]);
        l[i] = __float2bfloat16(f[i] - __bfloat162float(h[i]));
    }
    *(uint2*)(g_hxh + (size_t)c * DD + t * 4) = *(const uint2*)h;
    *(uint2*)(g_hxl + (size_t)c * DD + t * 4) = *(const uint2*)l;
}

// ---------------- 4b: Wp transpose + split; W1 transpose + split ----------------
__global__ void k_prepw(const float* __restrict__ Wp) {
    int i = blockIdx.x * blockDim.x + threadIdx.x;
    if (i >= DD * DD) return;
    int n = i >> 8, k = i & 255;
    float v = Wp[k * DD + n];
    __nv_bfloat16 h = __float2bfloat16(v);
    g_wph[n * DD + k] = h;
    g_wpl[n * DD + k] = __float2bfloat16(v - __bfloat162float(h));
}
__global__ void k_prepw1(const float* __restrict__ W1) {
    int i = blockIdx.x * blockDim.x + threadIdx.x;
    if (i >= NH * 128 * 64) return;
    int h = i >> 13;
    int n = (i >> 6) & 127;
    int k = i & 63;
    float v = W1[h * 8192 + k * 128 + n];
    __nv_bfloat16 hi = __float2bfloat16(v);
    g_w1h[i] = hi;
    g_w1l[i] = __float2bfloat16(v - __bfloat162float(hi));
}

// ---------------- 5: mma GEMM: xc = xcl + relu(hx @ Wp + bp) ----------------
// CTA tile 128x128, BK=32, 8 warps (4m x 2n), warp tile 32x64 (2x8 mma frags)
#define ASTR 40   // smem row stride in bf16 (32 data + 8 pad): conflict-free frag loads
__global__ void __launch_bounds__(256) k_gemm_mma(const float* __restrict__ xcl,
                                                  const float* __restrict__ bp,
                                                  float* __restrict__ xc) {
    __shared__ __nv_bfloat16 Ah[128 * ASTR], Al[128 * ASTR];
    __shared__ __nv_bfloat16 Bh[128 * ASTR], Bl[128 * ASTR];
    int tid = threadIdx.x;
    int lane = tid & 31, wid = tid >> 5;
    int g = lane >> 2, t = lane & 3;
    int wm = wid >> 1, wn = wid & 1;
    int bm = blockIdx.x * 128, bn = blockIdx.y * 128;
    float acc[2][8][4];
#pragma unroll
    for (int a = 0; a < 2; a++)
#pragma unroll
        for (int b = 0; b < 8; b++)
#pragma unroll
            for (int c = 0; c < 4; c++) acc[a][b][c] = 0.f;

    int lr = tid >> 1, lh = tid & 1;
    for (int kc = 0; kc < 8; kc++) {
        {
            int m = bm + lr;
            int4 vh0 = make_int4(0,0,0,0), vh1 = vh0, vl0 = vh0, vl1 = vh0;
            if (m < NC) {
                const int4* pH = (const int4*)(g_hxh + (size_t)m * DD + kc * 32 + lh * 16);
                const int4* pL = (const int4*)(g_hxl + (size_t)m * DD + kc * 32 + lh * 16);
                vh0 = pH[0]; vh1 = pH[1]; vl0 = pL[0]; vl1 = pL[1];
            }
            int so = lr * ASTR + lh * 16;
            *(int4*)(Ah + so) = vh0; *(int4*)(Ah + so + 8) = vh1;
            *(int4*)(Al + so) = vl0; *(int4*)(Al + so + 8) = vl1;
            int n = bn + lr;
            const int4* qH = (const int4*)(g_wph + (size_t)n * DD + kc * 32 + lh * 16);
            const int4* qL = (const int4*)(g_wpl + (size_t)n * DD + kc * 32 + lh * 16);
            *(int4*)(Bh + so) = qH[0]; *(int4*)(Bh + so + 8) = qH[1];
            *(int4*)(Bl + so) = qL[0]; *(int4*)(Bl + so + 8) = qL[1];
        }
        __syncthreads();
#pragma unroll
        for (int ks = 0; ks < 2; ks++) {
            int kb = ks * 16 + 2 * t;
            uint32_t ah[2][4], al[2][4], bhf[8][2], blf[8][2];
#pragma unroll
            for (int mi = 0; mi < 2; mi++) {
                int r = wm * 32 + mi * 16 + g;
                const __nv_bfloat16* p = Ah + r * ASTR + kb;
                const __nv_bfloat16* q = Al + r * ASTR + kb;
                ah[mi][0] = *(const uint32_t*)p;
                ah[mi][1] = *(const uint32_t*)(p + 8 * ASTR);
                ah[mi][2] = *(const uint32_t*)(p + 8);
                ah[mi][3] = *(const uint32_t*)(p + 8 * ASTR + 8);
                al[mi][0] = *(const uint32_t*)q;
                al[mi][1] = *(const uint32_t*)(q + 8 * ASTR);
                al[mi][2] = *(const uint32_t*)(q + 8);
                al[mi][3] = *(const uint32_t*)(q + 8 * ASTR + 8);
            }
#pragma unroll
            for (int ni = 0; ni < 8; ni++) {
                int n = wn * 64 + ni * 8 + g;
                const __nv_bfloat16* p = Bh + n * ASTR + kb;
                const __nv_bfloat16* q = Bl + n * ASTR + kb;
                bhf[ni][0] = *(const uint32_t*)p;
                bhf[ni][1] = *(const uint32_t*)(p + 8);
                blf[ni][0] = *(const uint32_t*)q;
                blf[ni][1] = *(const uint32_t*)(q + 8);
            }
#pragma unroll
            for (int mi = 0; mi < 2; mi++)
#pragma unroll
                for (int ni = 0; ni < 8; ni++) {
                    mma_bf16(acc[mi][ni], ah[mi], bhf[ni]);
                    mma_bf16(acc[mi][ni], ah[mi], blf[ni]);
                    mma_bf16(acc[mi][ni], al[mi], bhf[ni]);
                }
        }
        __syncthreads();
    }
    // epilogue: xc = xcl + relu(acc + bp)
#pragma unroll
    for (int mi = 0; mi < 2; mi++) {
        int r0 = bm + wm * 32 + mi * 16 + g;
        int r1 = r0 + 8;
#pragma unroll
        for (int ni = 0; ni < 8; ni++) {
            int col = bn + wn * 64 + ni * 8 + 2 * t;
            float2 bpv = *(const float2*)(bp + col);
            if (r0 < NC) {
                float2 xv = *(const float2*)(xcl + (size_t)r0 * DD + col);
                float2 o;
                o.x = xv.x + fmaxf(acc[mi][ni][0] + bpv.x, 0.f);
                o.y = xv.y + fmaxf(acc[mi][ni][1] + bpv.y, 0.f);
                *(float2*)(xc + (size_t)r0 * DD + col) = o;
            }
            if (r1 < NC) {
                float2 xv = *(const float2*)(xcl + (size_t)r1 * DD + col);
                float2 o;
                o.x = xv.x + fmaxf(acc[mi][ni][2] + bpv.x, 0.f);
                o.y = xv.y + fmaxf(acc[mi][ni][3] + bpv.y, 0.f);
                *(float2*)(xc + (size_t)r1 * DD + col) = o;
            }
        }
    }
}

// ---------------- 6: mma MLP score ----------------
// grid (ceil(NC/128), NH); 8 warps; warp = 16 rows x 128 cols; K=64
#define MSTR 72
#define MLP_SMEM (4 * 128 * MSTR * 2)
__global__ void __launch_bounds__(256) k_mlp_mma(const float* __restrict__ xc,
                                                 const float* __restrict__ b1,
                                                 const float* __restrict__ W2,
                                                 const float* __restrict__ b2) {
    extern __shared__ __nv_bfloat16 smm[];
    __nv_bfloat16* Ah = smm;
    __nv_bfloat16* Al = Ah + 128 * MSTR;
    __nv_bfloat16* Bh = Al + 128 * MSTR;
    __nv_bfloat16* Bl = Bh + 128 * MSTR;
    __shared__ float b1h[128], w2h[128];
    int h = blockIdx.y;
    int tid = threadIdx.x, lane = tid & 31, wid = tid >> 5;
    int g = lane >> 2, t = lane & 3;
    int bm = blockIdx.x * 128;
    if (tid < 128) { b1h[tid] = b1[h * 128 + tid]; w2h[tid] = W2[h * 128 + tid]; }
    for (int j = tid; j < 8192; j += 256) {
        int n = j >> 6, k = j & 63;
        Bh[n * MSTR + k] = g_w1h[h * 8192 + j];
        Bl[n * MSTR + k] = g_w1l[h * 8192 + j];
    }
    int lr = tid >> 1, lh = tid & 1;
    int m = bm + lr;
#pragma unroll
    for (int it = 0; it < 4; it++) {
        int kb = lh * 32 + it * 8;
        float f[8] = {0.f, 0.f, 0.f, 0.f, 0.f, 0.f, 0.f, 0.f};
        if (m < NC) {
            float4 v0 = *(const float4*)(xc + (size_t)m * DD + h * 64 + kb);
            float4 v1 = *(const float4*)(xc + (size_t)m * DD + h * 64 + kb + 4);
            f[0] = v0.x; f[1] = v0.y; f[2] = v0.z; f[3] = v0.w;
            f[4] = v1.x; f[5] = v1.y; f[6] = v1.z; f[7] = v1.w;
        }
        __nv_bfloat16 hh[8], ll[8];
#pragma unroll
        for (int j = 0; j < 8; j++) {
            hh[j] = __float2bfloat16(f[j]);
            ll[j] = __float2bfloat16(f[j] - __bfloat162float(hh[j]));
        }
        *(int4*)(Ah + lr * MSTR + kb) = *(const int4*)hh;
        *(int4*)(Al + lr * MSTR + kb) = *(const int4*)ll;
    }
    __syncthreads();
    float acc[16][4];
#pragma unroll
    for (int a = 0; a < 16; a++)
#pragma unroll
        for (int c = 0; c < 4; c++) acc[a][c] = 0.f;
#pragma unroll
    for (int ks = 0; ks < 4; ks++) {
        int kb = ks * 16 + 2 * t;
        int r = wid * 16 + g;
        uint32_t ah[4], al[4];
        const __nv_bfloat16* p = Ah + r * MSTR + kb;
        const __nv_bfloat16* q = Al + r * MSTR + kb;
        ah[0] = *(const uint32_t*)p;
        ah[1] = *(const uint32_t*)(p + 8 * MSTR);
        ah[2] = *(const uint32_t*)(p + 8);
        ah[3] = *(const uint32_t*)(p + 8 * MSTR + 8);
        al[0] = *(const uint32_t*)q;
        al[1] = *(const uint32_t*)(q + 8 * MSTR);
        al[2] = *(const uint32_t*)(q + 8);
        al[3] = *(const uint32_t*)(q + 8 * MSTR + 8);
#pragma unroll
        for (int ni = 0; ni < 16; ni++) {
            int n = ni * 8 + g;
            const __nv_bfloat16* bp_ = Bh + n * MSTR + kb;
            const __nv_bfloat16* bq_ = Bl + n * MSTR + kb;
            uint32_t bhf[2] = { *(const uint32_t*)bp_, *(const uint32_t*)(bp_ + 8) };
            uint32_t blf[2] = { *(const uint32_t*)bq_, *(const uint32_t*)(bq_ + 8) };
            mma_bf16(acc[ni], ah, bhf);
            mma_bf16(acc[ni], ah, blf);
            mma_bf16(acc[ni], al, bhf);
        }
    }
    float sg = 0.f, s8 = 0.f;
#pragma unroll
    for (int ni = 0; ni < 16; ni++) {
        int col = ni * 8 + 2 * t;
        float w0 = w2h[col], w1v = w2h[col + 1];
        float q0 = b1h[col], q1 = b1h[col + 1];
        sg += fmaxf(acc[ni][0] + q0, 0.f) * w0 + fmaxf(acc[ni][1] + q1, 0.f) * w1v;
        s8 += fmaxf(acc[ni][2] + q0, 0.f) * w0 + fmaxf(acc[ni][3] + q1, 0.f) * w1v;
    }
    sg += __shfl_xor_sync(0xFFFFFFFFu, sg, 1);
    sg += __shfl_xor_sync(0xFFFFFFFFu, sg, 2);
    s8 += __shfl_xor_sync(0xFFFFFFFFu, s8, 1);
    s8 += __shfl_xor_sync(0xFFFFFFFFu, s8, 2);
    if (t == 0) {
        float b2h = __ldg(b2 + h);
        int r0 = bm + wid * 16 + g;
        if (r0 < NC) g_score[r0 * NH + h] = sg + b2h;
        int r1 = r0 + 8;
        if (r1 < NC) g_score[r1 * NH + h] = s8 + b2h;
    }
}

// ---------------- 7: segment softmax ----------------
__global__ void k_segmax() {
    int i = blockIdx.x * blockDim.x + threadIdx.x;
    if (i >= NC * NH) return;
    int c = i >> 2, h = i & 3;
    atomicMax(&g_mxu[g_cb[c] * NH + h], f2u_ord(g_score[i]));
}
__global__ void k_segsum() {
    int i = blockIdx.x * blockDim.x + threadIdx.x;
    if (i >= NC * NH) return;
    int c = i >> 2, h = i & 3;
    int b = g_cb[c];
    float e = expf(g_score[i] - u2f_ord(g_mxu[b * NH + h]));
    g_score[i] = e;
    atomicAdd(&g_den[b * NH + h], e);
}
__global__ void k_alpha(float* __restrict__ alpha_out) {
    int i = blockIdx.x * blockDim.x + threadIdx.x;
    if (i >= NC * NH) return;
    int c = i >> 2, h = i & 3;
    alpha_out[i] = g_score[i] / (g_den[g_cb[c] * NH + h] + 1e-16f);
}

// ---------------- 8: drug_feat segment-sum ----------------
__global__ void k_final(const float* __restrict__ xc, const float* __restrict__ alpha,
                        float* __restrict__ drug) {
    int d = threadIdx.x;
    int hh = d >> 6;
    int c0 = blockIdx.x * 128;
    if (c0 >= NC) return;
    int cend = min(c0 + 128, NC);
    float acc = 0.f;
    int cur = g_cb[c0];
    for (int c = c0; c < cend; c++) {
        int b = g_cb[c];
        if (b != cur) {
            atomicAdd(&drug[(size_t)cur * DD + d], acc);
            acc = 0.f; cur = b;
        }
        acc += xc[(size_t)c * DD + d] * alpha[c * NH + hh];
    }
    atomicAdd(&drug[(size_t)cur * DD + d], acc);
}

// ---------------- launcher ----------------
extern "C" void kernel_launch(void* const* d_in, const int* in_sizes, int n_in,
                              void* d_out, int out_size) {
    const float* x    = (const float*)d_in[0];
    const float* xcl  = (const float*)d_in[1];
    const float* Wp   = (const float*)d_in[2];
    const float* bp   = (const float*)d_in[3];
    const float* W1   = (const float*)d_in[4];
    const float* b1   = (const float*)d_in[5];
    const float* W2   = (const float*)d_in[6];
    const float* b2   = (const float*)d_in[7];
    const void*  a2c  = d_in[8];
    const void*  cb   = d_in[9];

    float* out  = (float*)d_out;
    float* drug = out;
    float* xc   = out + (size_t)NB * DD;
    float* alph = out + (size_t)NB * DD + (size_t)NC * DD;

    cudaFuncSetAttribute(k_mlp_mma, cudaFuncAttributeMaxDynamicSharedMemorySize, MLP_SMEM);

    k_detect<<<1, 256>>>((const long long*)a2c);
    k_cvt<<<(2 * NE + 255) / 256, 256>>>(a2c, cb);
    k_init<<<(NB * DD + 255) / 256, 256>>>(drug);
    k_prepw<<<(DD * DD + 255) / 256, 256>>>(Wp);
    k_prepw1<<<(NH * 128 * 64 + 255) / 256, 256>>>(W1);
    k_hist<<<(NE + 255) / 256, 256>>>();
    int nscan = (NC + 2047) / 2048;
    k_scan_a<<<nscan, 256>>>();
    k_scan_b<<<1, 32>>>(nscan);
    k_scan_c<<<(NC + 255) / 256, 256>>>();
    k_fill<<<(NE + 255) / 256, 256>>>();
    k_agg<<<NC, 64>>>(x);
    {
        dim3 g((NC + 127) / 128, 2);
        k_gemm_mma<<<g, 256>>>(xcl, bp, xc);
    }
    {
        dim3 g((NC + 127) / 128, NH);
        k_mlp_mma<<<g, 256, MLP_SMEM>>>(xc, b1, W2, b2);
    }
    k_segmax<<<(NC * NH + 255) / 256, 256>>>();
    k_segsum<<<(NC * NH + 255) / 256, 256>>>();
    k_alpha<<<(NC * NH + 255) / 256, 256>>>(alph);
    k_final<<<(NC + 127) / 128, 256>>>(xc, alph, drug);
}

// round 5
// speedup vs baseline: 1.8601x; 1.1004x over previous
#include <cuda_runtime.h>
#include <cuda_bf16.h>
#include <math.h>
#include <stdint.h>

#define NA 500000
#define NC 250000
#define NE 1000000
#define NB 2048
#define DD 256
#define NH 4

// ---------------- scratch ----------------
__device__ __align__(16) __nv_bfloat16 g_hxh[(size_t)NC * DD];
__device__ __align__(16) __nv_bfloat16 g_hxl[(size_t)NC * DD];
__device__ __align__(16) __nv_bfloat16 g_wph[DD * DD];       // Wp^T hi [N][K]
__device__ __align__(16) __nv_bfloat16 g_wpl[DD * DD];       // Wp^T lo [N][K]
__device__ __align__(16) __nv_bfloat16 g_w1h[NH * 128 * 64]; // W1^T hi [h][n][k]
__device__ __align__(16) __nv_bfloat16 g_w1l[NH * 128 * 64]; // W1^T lo [h][n][k]
__device__ int      g_idx[2 * NE];
__device__ int      g_cb[NC];
__device__ int      g_cnt[NC];
__device__ int      g_off[NC + 1];
__device__ int      g_fill[NC];
__device__ int      g_csr[NE];
__device__ int      g_part[256];
__device__ float    g_score[NC * NH];
__device__ unsigned g_mxu[NB * NH];
__device__ float    g_den[NB * NH];
__device__ int      g_is32;

// ---------------- PTX helpers ----------------
__device__ __forceinline__ void mma_bf16(float* c, const uint32_t* a, const uint32_t* b) {
    asm volatile(
        "mma.sync.aligned.m16n8k16.row.col.f32.bf16.bf16.f32 "
        "{%0,%1,%2,%3}, {%4,%5,%6,%7}, {%8,%9}, {%0,%1,%2,%3};"
        : "+f"(c[0]), "+f"(c[1]), "+f"(c[2]), "+f"(c[3])
        : "r"(a[0]), "r"(a[1]), "r"(a[2]), "r"(a[3]), "r"(b[0]), "r"(b[1]));
}
__device__ __forceinline__ uint32_t smem_u32(const void* p) {
    uint32_t a;
    asm("{ .reg .u64 t; cvta.to.shared.u64 t, %1; cvt.u32.u64 %0, t; }" : "=r"(a) : "l"(p));
    return a;
}
__device__ __forceinline__ void cp_async16(uint32_t sa, const void* g) {
    asm volatile("cp.async.cg.shared.global [%0], [%1], 16;" :: "r"(sa), "l"(g));
}
__device__ __forceinline__ void cp_commit() { asm volatile("cp.async.commit_group;"); }
template <int N>
__device__ __forceinline__ void cp_wait() { asm volatile("cp.async.wait_group %0;" :: "n"(N)); }

__device__ __forceinline__ unsigned f2u_ord(float f) {
    unsigned u = __float_as_uint(f);
    return (u & 0x80000000u) ? ~u : (u | 0x80000000u);
}
__device__ __forceinline__ float u2f_ord(unsigned u) {
    return (u & 0x80000000u) ? __uint_as_float(u ^ 0x80000000u) : __uint_as_float(~u);
}
__device__ __forceinline__ int clampi(int v, int lo, int hi) {
    return v < lo ? lo : (v > hi ? hi : v);
}
__device__ __forceinline__ uint32_t pack_split(float f, __nv_bfloat16* lo) {
    __nv_bfloat16 h = __float2bfloat16(f);
    *lo = __float2bfloat16(f - __bfloat162float(h));
    return (uint32_t)*(const uint16_t*)&h;
}

// ---------------- dtype detect + cvt (+fused hist) ----------------
__global__ void k_detect(const long long* __restrict__ a2c) {
    __shared__ int s;
    if (threadIdx.x == 0) s = 0;
    __syncthreads();
    long long v = a2c[threadIdx.x];
    if (v < 0 || v >= 0x80000000LL) atomicOr(&s, 1);
    __syncthreads();
    if (threadIdx.x == 0) g_is32 = s;
}
__global__ void k_cvt(const void* __restrict__ a2c, const void* __restrict__ cb) {
    int i = blockIdx.x * blockDim.x + threadIdx.x;
    int is32 = g_is32;
    if (i < 2 * NE) {
        int v = is32 ? ((const int*)a2c)[i] : (int)(((const long long*)a2c)[i]);
        g_idx[i] = v;
        if (i >= NE) atomicAdd(&g_cnt[clampi(v, 0, NC - 1)], 1);
    }
    if (i < NC) {
        int v = is32 ? ((const int*)cb)[i] : (int)(((const long long*)cb)[i]);
        g_cb[i] = clampi(v, 0, NB - 1);
    }
}

// ---------------- init ----------------
__global__ void k_init(float* __restrict__ drug) {
    int i = blockIdx.x * blockDim.x + threadIdx.x;
    if (i < NB * DD) drug[i] = 0.f;
    if (i < NC) { g_cnt[i] = 0; g_fill[i] = 0; }
    if (i < NB * NH) { g_den[i] = 0.f; g_mxu[i] = f2u_ord(-3.0e38f); }
}

// ---------------- scan ----------------
__global__ void k_scan_a() {
    __shared__ int sums[256];
    int tid = threadIdx.x;
    int base = blockIdx.x * 2048 + tid * 8;
    int pre[8]; int s = 0;
#pragma unroll
    for (int j = 0; j < 8; j++) {
        int idx = base + j;
        int v = (idx < NC) ? g_cnt[idx] : 0;
        pre[j] = s; s += v;
    }
    sums[tid] = s;
    __syncthreads();
    for (int off = 1; off < 256; off <<= 1) {
        int t = (tid >= off) ? sums[tid - off] : 0;
        __syncthreads();
        sums[tid] += t;
        __syncthreads();
    }
    int excl = (tid == 0) ? 0 : sums[tid - 1];
#pragma unroll
    for (int j = 0; j < 8; j++) {
        int idx = base + j;
        if (idx < NC) g_off[idx] = excl + pre[j];
    }
    if (tid == 255) g_part[blockIdx.x] = sums[255];
}
__global__ void k_scan_b(int nb) {
    if (threadIdx.x == 0) {
        int s = 0;
        for (int i = 0; i < nb; i++) { int t = g_part[i]; g_part[i] = s; s += t; }
    }
}
__global__ void k_scan_c() {
    int i = blockIdx.x * blockDim.x + threadIdx.x;
    if (i < NC) g_off[i] += g_part[i >> 11];
}

// ---------------- CSR fill ----------------
__global__ void k_fill() {
    int i = blockIdx.x * blockDim.x + threadIdx.x;
    if (i >= NE) return;
    int c = clampi(g_idx[NE + i], 0, NC - 1);
    int r = clampi(g_idx[i], 0, NA - 1);
    int p = g_off[c] + atomicAdd(&g_fill[c], 1);
    if (p >= 0 && p < NE) g_csr[p] = r;
}

// ---------------- gather + mean -> split bf16 ----------------
__global__ void k_agg(const float* __restrict__ x) {
    int c = blockIdx.x;
    int t = threadIdx.x;  // 0..63
    int deg = g_cnt[c];
    int st  = g_off[c];
    float4 acc = make_float4(0.f, 0.f, 0.f, 0.f);
    int e = 0;
    for (; e + 2 <= deg; e += 2) {
        int r0 = g_csr[st + e], r1 = g_csr[st + e + 1];
        float4 a = ((const float4*)(x + (size_t)r0 * DD))[t];
        float4 b = ((const float4*)(x + (size_t)r1 * DD))[t];
        acc.x += a.x + b.x; acc.y += a.y + b.y;
        acc.z += a.z + b.z; acc.w += a.w + b.w;
    }
    if (e < deg) {
        int r0 = g_csr[st + e];
        float4 a = ((const float4*)(x + (size_t)r0 * DD))[t];
        acc.x += a.x; acc.y += a.y; acc.z += a.z; acc.w += a.w;
    }
    float inv = 1.f / (float)max(deg, 1);
    float f[4] = { acc.x * inv, acc.y * inv, acc.z * inv, acc.w * inv };
    __nv_bfloat16 h[4], l[4];
#pragma unroll
    for (int i = 0; i < 4; i++) {
        h[i] = __float2bfloat16(f[i]);
        l[i] = __float2bfloat16(f[i] - __bfloat162float(h[i]));
    }
    *(uint2*)(g_hxh + (size_t)c * DD + t * 4) = *(const uint2*)h;
    *(uint2*)(g_hxl + (size_t)c * DD + t * 4) = *(const uint2*)l;
}

// ---------------- weight prep ----------------
__global__ void k_prepw(const float* __restrict__ Wp) {
    int i = blockIdx.x * blockDim.x + threadIdx.x;
    if (i >= DD * DD) return;
    int n = i >> 8, k = i & 255;
    float v = Wp[k * DD + n];
    __nv_bfloat16 h = __float2bfloat16(v);
    g_wph[n * DD + k] = h;
    g_wpl[n * DD + k] = __float2bfloat16(v - __bfloat162float(h));
}
__global__ void k_prepw1(const float* __restrict__ W1) {
    int i = blockIdx.x * blockDim.x + threadIdx.x;
    if (i >= NH * 128 * 64) return;
    int h = i >> 13;
    int n = (i >> 6) & 127;
    int k = i & 63;
    float v = W1[h * 8192 + k * 128 + n];
    __nv_bfloat16 hi = __float2bfloat16(v);
    g_w1h[i] = hi;
    g_w1l[i] = __float2bfloat16(v - __bfloat162float(hi));
}

// ---------------- fused GEMM + MLP ----------------
// grid (ceil(NC/128), 2); 256 thr; bn half = heads {2bn, 2bn+1}; warp wn -> one head.
// Phase1: xc tile via double-buffered cp.async + 3-term split-bf16 mma.
// Phase2: stage xc split-bf16 in smem, per-head MLP mma + W2 reduce -> g_score.
#define ASTR 40
#define BUFB 40960                    // one phase-1 buffer set (Ah|Al|Bh|Bl)
#define XSTR 136
#define FUSED_SMEM (2 * BUFB)         // phase2 needs 69632+; 81920 covers both
__global__ void __launch_bounds__(256, 2) k_gemm_fused(const float* __restrict__ xcl,
                                                       const float* __restrict__ bp,
                                                       const float* __restrict__ b1,
                                                       const float* __restrict__ W2,
                                                       const float* __restrict__ b2,
                                                       float* __restrict__ xc) {
    extern __shared__ char dyn[];
    __shared__ float s_b1[2][128], s_w2[2][128];
    int tid = threadIdx.x;
    int lane = tid & 31, wid = tid >> 5;
    int g = lane >> 2, t = lane & 3;
    int wm = wid >> 1, wn = wid & 1;
    int bm = blockIdx.x * 128, bn = blockIdx.y * 128;
    int hd = blockIdx.y * 2;   // first head of this bn half

    if (tid < 256) {
        int hh = tid >> 7, c = tid & 127;
        s_b1[hh][c] = b1[(hd + hh) * 128 + c];
        s_w2[hh][c] = W2[(hd + hh) * 128 + c];
    }

    float acc[2][8][4];
#pragma unroll
    for (int a = 0; a < 2; a++)
#pragma unroll
        for (int b = 0; b < 8; b++)
#pragma unroll
            for (int c = 0; c < 4; c++) acc[a][b][c] = 0.f;

    int lr = tid >> 1, lh = tid & 1;
    int msafe = min(bm + lr, NC - 1);
    int nrow = bn + lr;
    uint32_t so = (uint32_t)(lr * ASTR + lh * 16) * 2;  // byte offset in tile
    uint32_t sbase = smem_u32(dyn);

    // stage chunk kc into buffer buf
    auto stage = [&](int buf, int kc) {
        uint32_t sa = sbase + buf * BUFB + so;
        const char* gAh = (const char*)(g_hxh + (size_t)msafe * DD + kc * 32 + lh * 16);
        const char* gAl = (const char*)(g_hxl + (size_t)msafe * DD + kc * 32 + lh * 16);
        const char* gBh = (const char*)(g_wph + (size_t)nrow * DD + kc * 32 + lh * 16);
        const char* gBl = (const char*)(g_wpl + (size_t)nrow * DD + kc * 32 + lh * 16);
        cp_async16(sa + 0 * 10240,      gAh);      cp_async16(sa + 0 * 10240 + 16, gAh + 16);
        cp_async16(sa + 1 * 10240,      gAl);      cp_async16(sa + 1 * 10240 + 16, gAl + 16);
        cp_async16(sa + 2 * 10240,      gBh);      cp_async16(sa + 2 * 10240 + 16, gBh + 16);
        cp_async16(sa + 3 * 10240,      gBl);      cp_async16(sa + 3 * 10240 + 16, gBl + 16);
    };

    stage(0, 0); cp_commit();
    for (int kc = 0; kc < 8; kc++) {
        if (kc < 7) { stage((kc + 1) & 1, kc + 1); cp_commit(); cp_wait<1>(); }
        else cp_wait<0>();
        __syncthreads();
        const __nv_bfloat16* Ah = (const __nv_bfloat16*)(dyn + (kc & 1) * BUFB);
        const __nv_bfloat16* Al = Ah + 128 * ASTR;
        const __nv_bfloat16* Bh = Al + 128 * ASTR;
        const __nv_bfloat16* Bl = Bh + 128 * ASTR;
#pragma unroll
        for (int ks = 0; ks < 2; ks++) {
            int kb = ks * 16 + 2 * t;
            uint32_t ah[2][4], al[2][4], bhf[8][2], blf[8][2];
#pragma unroll
            for (int mi = 0; mi < 2; mi++) {
                int r = wm * 32 + mi * 16 + g;
                const __nv_bfloat16* p = Ah + r * ASTR + kb;
                const __nv_bfloat16* q = Al + r * ASTR + kb;
                ah[mi][0] = *(const uint32_t*)p;
                ah[mi][1] = *(const uint32_t*)(p + 8 * ASTR);
                ah[mi][2] = *(const uint32_t*)(p + 8);
                ah[mi][3] = *(const uint32_t*)(p + 8 * ASTR + 8);
                al[mi][0] = *(const uint32_t*)q;
                al[mi][1] = *(const uint32_t*)(q + 8 * ASTR);
                al[mi][2] = *(const uint32_t*)(q + 8);
                al[mi][3] = *(const uint32_t*)(q + 8 * ASTR + 8);
            }
#pragma unroll
            for (int ni = 0; ni < 8; ni++) {
                int n = wn * 64 + ni * 8 + g;
                const __nv_bfloat16* p = Bh + n * ASTR + kb;
                const __nv_bfloat16* q = Bl + n * ASTR + kb;
                bhf[ni][0] = *(const uint32_t*)p;
                bhf[ni][1] = *(const uint32_t*)(p + 8);
                blf[ni][0] = *(const uint32_t*)q;
                blf[ni][1] = *(const uint32_t*)(q + 8);
            }
#pragma unroll
            for (int mi = 0; mi < 2; mi++)
#pragma unroll
                for (int ni = 0; ni < 8; ni++) {
                    mma_bf16(acc[mi][ni], ah[mi], bhf[ni]);
                    mma_bf16(acc[mi][ni], ah[mi], blf[ni]);
                    mma_bf16(acc[mi][ni], al[mi], bhf[ni]);
                }
        }
        __syncthreads();
    }

    // ---- epilogue: xc = xcl + relu(acc + bp); write global + stage split bf16 ----
    __nv_bfloat16* xcH = (__nv_bfloat16*)dyn;
    __nv_bfloat16* xcL = xcH + 128 * XSTR;
#pragma unroll
    for (int mi = 0; mi < 2; mi++) {
        int rr0 = wm * 32 + mi * 16 + g;       // row within tile
        int rr1 = rr0 + 8;
        int r0 = bm + rr0, r1 = bm + rr1;
#pragma unroll
        for (int ni = 0; ni < 8; ni++) {
            int colrel = wn * 64 + ni * 8 + 2 * t;
            int col = bn + colrel;
            float2 bpv = *(const float2*)(bp + col);
            float o0 = fmaxf(acc[mi][ni][0] + bpv.x, 0.f);
            float o1 = fmaxf(acc[mi][ni][1] + bpv.y, 0.f);
            float o2 = fmaxf(acc[mi][ni][2] + bpv.x, 0.f);
            float o3 = fmaxf(acc[mi][ni][3] + bpv.y, 0.f);
            if (r0 < NC) {
                float2 xv = *(const float2*)(xcl + (size_t)r0 * DD + col);
                o0 += xv.x; o1 += xv.y;
                float2 w = make_float2(o0, o1);
                *(float2*)(xc + (size_t)r0 * DD + col) = w;
            }
            if (r1 < NC) {
                float2 xv = *(const float2*)(xcl + (size_t)r1 * DD + col);
                o2 += xv.x; o3 += xv.y;
                float2 w = make_float2(o2, o3);
                *(float2*)(xc + (size_t)r1 * DD + col) = w;
            }
            // split & stage (garbage ok for rows >= NC; outputs guarded)
            __nv_bfloat16 l0, l1, l2, l3;
            uint32_t h0 = pack_split(o0, &l0), h1 = pack_split(o1, &l1);
            uint32_t h2 = pack_split(o2, &l2), h3 = pack_split(o3, &l3);
            *(uint32_t*)&xcH[rr0 * XSTR + colrel] = h0 | (h1 << 16);
            *(uint32_t*)&xcH[rr1 * XSTR + colrel] = h2 | (h3 << 16);
            uint16_t ul0 = *(const uint16_t*)&l0, ul1 = *(const uint16_t*)&l1;
            uint16_t ul2 = *(const uint16_t*)&l2, ul3 = *(const uint16_t*)&l3;
            *(uint32_t*)&xcL[rr0 * XSTR + colrel] = (uint32_t)ul0 | ((uint32_t)ul1 << 16);
            *(uint32_t*)&xcL[rr1 * XSTR + colrel] = (uint32_t)ul2 | ((uint32_t)ul3 << 16);
        }
    }
    __syncthreads();

    // ---- phase 2: per-head MLP. warp wn -> head hd+wn; rows wm*32..+32 ----
    int h = hd + wn;
    uint32_t mh[2][4][4], ml[2][4][4];   // [mi][ks][reg]
#pragma unroll
    for (int mi = 0; mi < 2; mi++)
#pragma unroll
        for (int ks = 0; ks < 4; ks++) {
            int rb = (wm * 32 + mi * 16 + g) * XSTR + wn * 64 + ks * 16 + 2 * t;
            mh[mi][ks][0] = *(const uint32_t*)&xcH[rb];
            mh[mi][ks][1] = *(const uint32_t*)&xcH[rb + 8 * XSTR];
            mh[mi][ks][2] = *(const uint32_t*)&xcH[rb + 8];
            mh[mi][ks][3] = *(const uint32_t*)&xcH[rb + 8 * XSTR + 8];
            ml[mi][ks][0] = *(const uint32_t*)&xcL[rb];
            ml[mi][ks][1] = *(const uint32_t*)&xcL[rb + 8 * XSTR];
            ml[mi][ks][2] = *(const uint32_t*)&xcL[rb + 8];
            ml[mi][ks][3] = *(const uint32_t*)&xcL[rb + 8 * XSTR + 8];
        }
    float s0[2] = {0.f, 0.f}, s1[2] = {0.f, 0.f};
#pragma unroll
    for (int nj = 0; nj < 16; nj++) {
        float a2[2][4] = {{0.f,0.f,0.f,0.f},{0.f,0.f,0.f,0.f}};
        int n = nj * 8 + g;
#pragma unroll
        for (int ks = 0; ks < 4; ks++) {
            int koff = h * 8192 + n * 64 + ks * 16 + 2 * t;
            uint32_t bh[2], bl[2];
            bh[0] = *(const uint32_t*)&g_w1h[koff];
            bh[1] = *(const uint32_t*)&g_w1h[koff + 8];
            bl[0] = *(const uint32_t*)&g_w1l[koff];
            bl[1] = *(const uint32_t*)&g_w1l[koff + 8];
#pragma unroll
            for (int mi = 0; mi < 2; mi++) {
                mma_bf16(a2[mi], mh[mi][ks], bh);
                mma_bf16(a2[mi], mh[mi][ks], bl);
                mma_bf16(a2[mi], ml[mi][ks], bh);
            }
        }
        int col = nj * 8 + 2 * t;
        float w0 = s_w2[wn][col], w1v = s_w2[wn][col + 1];
        float q0 = s_b1[wn][col], q1 = s_b1[wn][col + 1];
#pragma unroll
        for (int mi = 0; mi < 2; mi++) {
            s0[mi] += fmaxf(a2[mi][0] + q0, 0.f) * w0 + fmaxf(a2[mi][1] + q1, 0.f) * w1v;
            s1[mi] += fmaxf(a2[mi][2] + q0, 0.f) * w0 + fmaxf(a2[mi][3] + q1, 0.f) * w1v;
        }
    }
#pragma unroll
    for (int mi = 0; mi < 2; mi++) {
        s0[mi] += __shfl_xor_sync(0xFFFFFFFFu, s0[mi], 1);
        s0[mi] += __shfl_xor_sync(0xFFFFFFFFu, s0[mi], 2);
        s1[mi] += __shfl_xor_sync(0xFFFFFFFFu, s1[mi], 1);
        s1[mi] += __shfl_xor_sync(0xFFFFFFFFu, s1[mi], 2);
    }
    if (t == 0) {
        float b2h = __ldg(b2 + h);
#pragma unroll
        for (int mi = 0; mi < 2; mi++) {
            int r0 = bm + wm * 32 + mi * 16 + g;
            if (r0 < NC) g_score[r0 * NH + h] = s0[mi] + b2h;
            if (r0 + 8 < NC) g_score[(r0 + 8) * NH + h] = s1[mi] + b2h;
        }
    }
}

// ---------------- segment softmax ----------------
__global__ void k_segmax() {
    int i = blockIdx.x * blockDim.x + threadIdx.x;
    if (i >= NC * NH) return;
    int c = i >> 2, h = i & 3;
    atomicMax(&g_mxu[g_cb[c] * NH + h], f2u_ord(g_score[i]));
}
__global__ void k_segsum() {
    int i = blockIdx.x * blockDim.x + threadIdx.x;
    if (i >= NC * NH) return;
    int c = i >> 2, h = i & 3;
    int b = g_cb[c];
    float e = expf(g_score[i] - u2f_ord(g_mxu[b * NH + h]));
    g_score[i] = e;
    atomicAdd(&g_den[b * NH + h], e);
}
__global__ void k_alpha(float* __restrict__ alpha_out) {
    int i = blockIdx.x * blockDim.x + threadIdx.x;
    if (i >= NC * NH) return;
    int c = i >> 2, h = i & 3;
    alpha_out[i] = g_score[i] / (g_den[g_cb[c] * NH + h] + 1e-16f);
}

// ---------------- drug_feat segment-sum ----------------
__global__ void k_final(const float* __restrict__ xc, const float* __restrict__ alpha,
                        float* __restrict__ drug) {
    int d = threadIdx.x;
    int hh = d >> 6;
    int c0 = blockIdx.x * 128;
    if (c0 >= NC) return;
    int cend = min(c0 + 128, NC);
    float acc = 0.f;
    int cur = g_cb[c0];
    for (int c = c0; c < cend; c++) {
        int b = g_cb[c];
        if (b != cur) {
            atomicAdd(&drug[(size_t)cur * DD + d], acc);
            acc = 0.f; cur = b;
        }
        acc += xc[(size_t)c * DD + d] * alpha[c * NH + hh];
    }
    atomicAdd(&drug[(size_t)cur * DD + d], acc);
}

// ---------------- launcher ----------------
extern "C" void kernel_launch(void* const* d_in, const int* in_sizes, int n_in,
                              void* d_out, int out_size) {
    const float* x    = (const float*)d_in[0];
    const float* xcl  = (const float*)d_in[1];
    const float* Wp   = (const float*)d_in[2];
    const float* bp   = (const float*)d_in[3];
    const float* W1   = (const float*)d_in[4];
    const float* b1   = (const float*)d_in[5];
    const float* W2   = (const float*)d_in[6];
    const float* b2   = (const float*)d_in[7];
    const void*  a2c  = d_in[8];
    const void*  cb   = d_in[9];

    float* out  = (float*)d_out;
    float* drug = out;
    float* xc   = out + (size_t)NB * DD;
    float* alph = out + (size_t)NB * DD + (size_t)NC * DD;

    cudaFuncSetAttribute(k_gemm_fused, cudaFuncAttributeMaxDynamicSharedMemorySize, FUSED_SMEM);

    k_detect<<<1, 256>>>((const long long*)a2c);
    k_init<<<(NB * DD + 255) / 256, 256>>>(drug);
    k_cvt<<<(2 * NE + 255) / 256, 256>>>(a2c, cb);
    int nscan = (NC + 2047) / 2048;
    k_scan_a<<<nscan, 256>>>();
    k_scan_b<<<1, 32>>>(nscan);
    k_scan_c<<<(NC + 255) / 256, 256>>>();
    k_fill<<<(NE + 255) / 256, 256>>>();
    k_agg<<<NC, 64>>>(x);
    k_prepw<<<(DD * DD + 255) / 256, 256>>>(Wp);
    k_prepw1<<<(NH * 128 * 64 + 255) / 256, 256>>>(W1);
    {
        dim3 g((NC + 127) / 128, 2);
        k_gemm_fused<<<g, 256, FUSED_SMEM>>>(xcl, bp, b1, W2, b2, xc);
    }
    k_segmax<<<(NC * NH + 255) / 256, 256>>>();
    k_segsum<<<(NC * NH + 255) / 256, 256>>>();
    k_alpha<<<(NC * NH + 255) / 256, 256>>>(alph);
    k_final<<<(NC + 127) / 128, 256>>>(xc, alph, drug);
}